// round 16
// baseline (speedup 1.0000x reference)
#include <cuda_runtime.h>
#include <cuda_bf16.h>
#include <math.h>
#include <stdint.h>

#define Bsz   32
#define Ssz   1024
#define Dsz   1280
#define CRS   768
#define HEADS 20
#define HD    64
#define NTOK  16
#define ETOK  48
#define MS    (Bsz*Ssz)
#define SCALE 0.125f

typedef __nv_bfloat16 bf16;

// ---------------- scratch (device globals: allocation-free) ----------------
__device__ bf16  g_z  [MS*Dsz];
__device__ bf16  g_hidb[MS*Dsz];
__device__ bf16  g_anat[Bsz*NTOK*CRS];
__device__ bf16  g_dis [Bsz*NTOK*CRS];
__device__ float g_ka [Bsz*NTOK*Dsz];
__device__ float g_va [Bsz*NTOK*Dsz];
__device__ float g_kd [Bsz*NTOK*Dsz];
__device__ float g_vd [Bsz*NTOK*Dsz];
__device__ float g_gate[Bsz*2];
__device__ bf16  g_wq  [Dsz*Dsz];
__device__ bf16  g_wout[Dsz*Dsz];
__device__ bf16  g_wka [Dsz*CRS];
__device__ bf16  g_wva [Dsz*CRS];
__device__ bf16  g_wkd [Dsz*CRS];
__device__ bf16  g_wvd [Dsz*CRS];

// ---------------- helpers ---------------------------------------------------
__device__ __forceinline__ uint32_t smem_u32(const void* p) {
    uint32_t a;
    asm("{ .reg .u64 t; cvta.to.shared.u64 t, %1; cvt.u32.u64 %0, t; }" : "=r"(a) : "l"(p));
    return a;
}
__device__ __forceinline__ void cp16(uint32_t dst, const void* src) {
    asm volatile("cp.async.cg.shared.global [%0], [%1], 16;" :: "r"(dst), "l"(src));
}
#define CP_COMMIT() asm volatile("cp.async.commit_group;" ::: "memory")

__device__ __forceinline__ uint32_t pack_bf2(float lo, float hi) {
    __nv_bfloat162 v = __floats2bfloat162_rn(lo, hi);
    return *(uint32_t*)&v;
}
__device__ __forceinline__ void ldsm4(uint32_t* r, uint32_t addr) {
    asm volatile("ldmatrix.sync.aligned.m8n8.x4.shared.b16 {%0,%1,%2,%3}, [%4];"
                 : "=r"(r[0]), "=r"(r[1]), "=r"(r[2]), "=r"(r[3]) : "r"(addr));
}
__device__ __forceinline__ void mma16(float* d, const uint32_t* a, const uint32_t* b) {
    asm volatile(
        "mma.sync.aligned.m16n8k16.row.col.f32.bf16.bf16.f32 "
        "{%0,%1,%2,%3}, {%4,%5,%6,%7}, {%8,%9}, {%0,%1,%2,%3};"
        : "+f"(d[0]), "+f"(d[1]), "+f"(d[2]), "+f"(d[3])
        : "r"(a[0]), "r"(a[1]), "r"(a[2]), "r"(a[3]), "r"(b[0]), "r"(b[1]));
}

#define LDE 72
#define TILE_E (128*LDE)
#define TILE_BYTES (TILE_E*2)            // 18432
#define STAGE_BYTES (2*TILE_BYTES)       // 36864
#define GEMM_SMEM (3*STAGE_BYTES)        // 110592 (2 CTAs/SM)
#define VP 24

// ================= 8-warp GEMM core (R11/R15): warp tile 64x32 ==============
__device__ __forceinline__ void gemm_core8(
    const bf16* __restrict__ A, const bf16* __restrict__ W,
    float* __restrict__ C, int N, int K, int bm, int bn,
    const float* __restrict__ bias, const float* __restrict__ res,
    uint32_t sbase, int t, int lane, int warp_m, int warp_n)
{
    const int NIT = K / 64;

    const uint32_t aLane = ((uint32_t)(warp_m*64 + (lane & 15)) * LDE
                          + ((lane >> 4) << 3)) * 2;
    const uint32_t bLane = ((uint32_t)(warp_n*32 + ((lane >> 4) << 3) + (lane & 7)) * LDE
                          + (((lane >> 3) & 1) << 3)) * 2;

    float acc[4][4][4];
    #pragma unroll
    for (int i = 0; i < 4; i++)
        #pragma unroll
        for (int j = 0; j < 4; j++)
            #pragma unroll
            for (int r = 0; r < 4; r++) acc[i][j][r] = 0.f;

    #define LOAD_STAGE8(IT, S) do {                                            \
        const bf16* Ab = A + (long)bm * K + (IT) * 64;                         \
        const bf16* Wb = W + (long)bn * K + (IT) * 64;                         \
        uint32_t dA = sbase + (S) * STAGE_BYTES;                               \
        uint32_t dB = dA + TILE_BYTES;                                         \
        _Pragma("unroll")                                                      \
        for (int i = 0; i < 4; i++) {                                          \
            int idx = i * 256 + t; int row = idx >> 3, g = idx & 7;            \
            cp16(dA + row * (LDE*2) + g * 16, Ab + (long)row * K + g * 8);     \
        }                                                                      \
        _Pragma("unroll")                                                      \
        for (int i = 0; i < 4; i++) {                                          \
            int idx = i * 256 + t; int row = idx >> 3, g = idx & 7;            \
            cp16(dB + row * (LDE*2) + g * 16, Wb + (long)row * K + g * 8);     \
        }                                                                      \
        CP_COMMIT();                                                           \
    } while (0)

    LOAD_STAGE8(0, 0);
    if (NIT > 1) LOAD_STAGE8(1, 1);

    for (int it = 0; it < NIT; it++) {
        int s = it % 3;
        if (it + 1 < NIT) asm volatile("cp.async.wait_group 1;" ::: "memory");
        else              asm volatile("cp.async.wait_group 0;" ::: "memory");
        __syncthreads();
        if (it + 2 < NIT)
            LOAD_STAGE8(it + 2, (it + 2) % 3);

        const uint32_t aBase = sbase + s * STAGE_BYTES + aLane;
        const uint32_t bBase = sbase + s * STAGE_BYTES + TILE_BYTES + bLane;
        #pragma unroll
        for (int ks = 0; ks < 4; ks++) {
            uint32_t a[4][4], bb[2][4];
            #pragma unroll
            for (int mt = 0; mt < 4; mt++)
                ldsm4(a[mt], aBase + mt * (16*LDE*2) + ks * 32);
            #pragma unroll
            for (int j = 0; j < 2; j++)
                ldsm4(bb[j], bBase + j * (16*LDE*2) + ks * 32);
            #pragma unroll
            for (int mt = 0; mt < 4; mt++)
                #pragma unroll
                for (int nt = 0; nt < 4; nt++)
                    mma16(acc[mt][nt], a[mt], &bb[nt >> 1][(nt & 1) * 2]);
        }
    }

    #pragma unroll
    for (int mt = 0; mt < 4; mt++) {
        #pragma unroll
        for (int nt = 0; nt < 4; nt++) {
            int row = bm + warp_m * 64 + mt * 16 + (lane >> 2);
            int col = bn + warp_n * 32 + nt * 8 + 2 * (lane & 3);
            float2 v0 = make_float2(acc[mt][nt][0], acc[mt][nt][1]);
            float2 v1 = make_float2(acc[mt][nt][2], acc[mt][nt][3]);
            if (bias) {
                float2 bb2 = *(const float2*)(bias + col);
                v0.x += bb2.x; v0.y += bb2.y; v1.x += bb2.x; v1.y += bb2.y;
            }
            if (res) {
                float2 r0 = *(const float2*)(res + (long)row * N + col);
                float2 r1 = *(const float2*)(res + (long)(row + 8) * N + col);
                v0.x += r0.x; v0.y += r0.y; v1.x += r1.x; v1.y += r1.y;
            }
            *(float2*)(C + (long)row * N + col) = v0;
            *(float2*)(C + (long)(row + 8) * N + col) = v1;
        }
    }
    #undef LOAD_STAGE8
}

// KV projections: grid (10, 16), 256 threads. y: e=y>>2, bm=(y&3)*128
struct KvBatch { const bf16* A[4]; const bf16* W[4]; float* C[4]; };

__global__ __launch_bounds__(256, 2)
void kv_proj(KvBatch kb) {
    extern __shared__ bf16 sm[];
    const int t = threadIdx.x;
    const int lane = t & 31, wid = t >> 5;
    int e = blockIdx.y >> 2, bm = (blockIdx.y & 3) * 128;
    gemm_core8(kb.A[e], kb.W[e], kb.C[e], Dsz, CRS, bm, blockIdx.x * 128,
               nullptr, nullptr, smem_u32(sm), t, lane, wid >> 2, wid & 3);
}

__global__ __launch_bounds__(256, 2)
void gemm_out(const bf16* __restrict__ A, const bf16* __restrict__ W,
              float* __restrict__ C,
              const float* __restrict__ bias, const float* __restrict__ res) {
    extern __shared__ bf16 sm[];
    const int t = threadIdx.x;
    const int lane = t & 31, wid = t >> 5;
    gemm_core8(A, W, C, Dsz, Dsz, blockIdx.y * 128, blockIdx.x * 128,
               bias, res, smem_u32(sm), t, lane, wid >> 2, wid & 3);
}

// ================= fused Q projection + attention ============================
// 4 warps (2m x 2n), warp tile 64x64 = 64 queries x 1 full head.
// KV smem offsets (bf16 elems) inside freed stage-0 region:
#define KV_KA 0
#define KV_KD 2304
#define KV_VA 4608
#define KV_VD 7680

__device__ __forceinline__ void attend_one(
    const bf16* sK, const bf16* sV, float gate, int lane,
    const uint32_t (&qf)[4][4], float (&out)[8][4])
{
    uint32_t bk[2][4][2];
    #pragma unroll
    for (int n = 0; n < 2; n++)
        #pragma unroll
        for (int k = 0; k < 4; k++) {
            const bf16* p = &sK[(n*8 + (lane >> 2))*72 + k*16 + 2*(lane & 3)];
            bk[n][k][0] = *(const uint32_t*)p;
            bk[n][k][1] = *(const uint32_t*)(p + 8);
        }
    uint32_t bv[8][2];
    #pragma unroll
    for (int n8 = 0; n8 < 8; n8++) {
        const bf16* p = &sV[(n8*8 + (lane >> 2))*VP + 2*(lane & 3)];
        bv[n8][0] = *(const uint32_t*)p;
        bv[n8][1] = *(const uint32_t*)(p + 8);
    }

    float sc[2][4];
    #pragma unroll
    for (int n = 0; n < 2; n++) {
        #pragma unroll
        for (int r = 0; r < 4; r++) sc[n][r] = 0.f;
        #pragma unroll
        for (int k = 0; k < 4; k++)
            mma16(sc[n], qf[k], bk[n][k]);
    }

    float v[2][4];
    #pragma unroll
    for (int n = 0; n < 2; n++)
        #pragma unroll
        for (int r = 0; r < 4; r++) v[n][r] = sc[n][r] * SCALE;

    float mx0 = fmaxf(fmaxf(v[0][0], v[0][1]), fmaxf(v[1][0], v[1][1]));
    float mx1 = fmaxf(fmaxf(v[0][2], v[0][3]), fmaxf(v[1][2], v[1][3]));
    mx0 = fmaxf(mx0, __shfl_xor_sync(0xffffffffu, mx0, 1));
    mx0 = fmaxf(mx0, __shfl_xor_sync(0xffffffffu, mx0, 2));
    mx1 = fmaxf(mx1, __shfl_xor_sync(0xffffffffu, mx1, 1));
    mx1 = fmaxf(mx1, __shfl_xor_sync(0xffffffffu, mx1, 2));

    float e[2][4];
    #pragma unroll
    for (int n = 0; n < 2; n++) {
        e[n][0] = expf(v[n][0] - mx0);
        e[n][1] = expf(v[n][1] - mx0);
        e[n][2] = expf(v[n][2] - mx1);
        e[n][3] = expf(v[n][3] - mx1);
    }
    float s0 = e[0][0] + e[0][1] + e[1][0] + e[1][1];
    float s1 = e[0][2] + e[0][3] + e[1][2] + e[1][3];
    s0 += __shfl_xor_sync(0xffffffffu, s0, 1);
    s0 += __shfl_xor_sync(0xffffffffu, s0, 2);
    s1 += __shfl_xor_sync(0xffffffffu, s1, 1);
    s1 += __shfl_xor_sync(0xffffffffu, s1, 2);
    float i0 = gate / s0, i1 = gate / s1;

    uint32_t pf[4];
    pf[0] = pack_bf2(e[0][0]*i0, e[0][1]*i0);
    pf[1] = pack_bf2(e[0][2]*i1, e[0][3]*i1);
    pf[2] = pack_bf2(e[1][0]*i0, e[1][1]*i0);
    pf[3] = pack_bf2(e[1][2]*i1, e[1][3]*i1);

    #pragma unroll
    for (int n8 = 0; n8 < 8; n8++)
        mma16(out[n8], pf, bv[n8]);
}

__global__ __launch_bounds__(128, 2)
void qproj_attn(const bf16* __restrict__ A, const bf16* __restrict__ W) {
    extern __shared__ bf16 sm[];
    const int t = threadIdx.x;
    const int lane = t & 31, wid = t >> 5;
    const int warp_m = wid >> 1, warp_n = wid & 1;
    const int bm = blockIdx.y * 128, bn = blockIdx.x * 128;
    const uint32_t sbase = smem_u32(sm);
    const int NIT = Dsz / 64;

    const uint32_t aLane = ((uint32_t)(warp_m*64 + (lane & 15)) * LDE
                          + ((lane >> 4) << 3)) * 2;
    const uint32_t bLane = ((uint32_t)(warp_n*64 + ((lane >> 4) << 3) + (lane & 7)) * LDE
                          + (((lane >> 3) & 1) << 3)) * 2;

    float acc[4][8][4];
    #pragma unroll
    for (int i = 0; i < 4; i++)
        #pragma unroll
        for (int j = 0; j < 8; j++)
            #pragma unroll
            for (int r = 0; r < 4; r++) acc[i][j][r] = 0.f;

    #define LOAD_STAGE4(IT, S) do {                                            \
        const bf16* Ab = A + (long)bm * Dsz + (IT) * 64;                       \
        const bf16* Wb = W + (long)bn * Dsz + (IT) * 64;                       \
        uint32_t dA = sbase + (S) * STAGE_BYTES;                               \
        uint32_t dB = dA + TILE_BYTES;                                         \
        _Pragma("unroll")                                                      \
        for (int i = 0; i < 8; i++) {                                          \
            int idx = i * 128 + t; int row = idx >> 3, g = idx & 7;            \
            cp16(dA + row * (LDE*2) + g * 16, Ab + (long)row * Dsz + g * 8);   \
        }                                                                      \
        _Pragma("unroll")                                                      \
        for (int i = 0; i < 8; i++) {                                          \
            int idx = i * 128 + t; int row = idx >> 3, g = idx & 7;            \
            cp16(dB + row * (LDE*2) + g * 16, Wb + (long)row * Dsz + g * 8);   \
        }                                                                      \
        CP_COMMIT();                                                           \
    } while (0)

    LOAD_STAGE4(0, 0);
    LOAD_STAGE4(1, 1);

    for (int it = 0; it < NIT; it++) {
        int s = it % 3;
        if (it + 1 < NIT) asm volatile("cp.async.wait_group 1;" ::: "memory");
        else              asm volatile("cp.async.wait_group 0;" ::: "memory");
        __syncthreads();
        if (it + 2 < NIT)
            LOAD_STAGE4(it + 2, (it + 2) % 3);

        const uint32_t aBase = sbase + s * STAGE_BYTES + aLane;
        const uint32_t bBase = sbase + s * STAGE_BYTES + TILE_BYTES + bLane;
        #pragma unroll
        for (int ks = 0; ks < 4; ks++) {
            uint32_t a[4][4], bb[4][4];
            #pragma unroll
            for (int mt = 0; mt < 4; mt++)
                ldsm4(a[mt], aBase + mt * (16*LDE*2) + ks * 32);
            #pragma unroll
            for (int j = 0; j < 4; j++)
                ldsm4(bb[j], bBase + j * (16*LDE*2) + ks * 32);
            #pragma unroll
            for (int mt = 0; mt < 4; mt++)
                #pragma unroll
                for (int nt = 0; nt < 8; nt++)
                    mma16(acc[mt][nt], a[mt], &bb[nt >> 1][(nt & 1) * 2]);
        }
    }
    #undef LOAD_STAGE4

    // ---- load KV for this CTA's 2 heads into freed stage-0 smem ----
    __syncthreads();
    const int b = bm >> 10;                 // batch (bm / Ssz)
    const int h0 = 2 * blockIdx.x;
    for (int i = t; i < 2*NTOK*32; i += 128) {        // K: float2 over 64 dims
        int hh = i >= NTOK*32;
        int rem = i - hh*NTOK*32;
        int tok = rem >> 5, d2 = rem & 31;
        long src = ((long)(b*NTOK + tok))*Dsz + (h0+hh)*HD + 2*d2;
        float2 va = *(const float2*)(g_ka + src);
        float2 vd = *(const float2*)(g_kd + src);
        *(uint32_t*)&sm[KV_KA + hh*1152 + tok*72 + 2*d2] = pack_bf2(va.x, va.y);
        *(uint32_t*)&sm[KV_KD + hh*1152 + tok*72 + 2*d2] = pack_bf2(vd.x, vd.y);
    }
    for (int i = t; i < 2*64*NTOK; i += 128) {        // V transposed [d][tok]
        int hh = i >= 64*NTOK;
        int rem = i - hh*64*NTOK;
        int d = rem & 63, tok = rem >> 6;
        long src = ((long)(b*NTOK + tok))*Dsz + (h0+hh)*HD + d;
        sm[KV_VA + hh*1536 + d*VP + tok] = __float2bfloat16_rn(g_va[src]);
        sm[KV_VD + hh*1536 + d*VP + tok] = __float2bfloat16_rn(g_vd[src]);
    }
    __syncthreads();

    const float ga = g_gate[b*2+0], gd = g_gate[b*2+1];
    const bf16* sKa = sm + KV_KA + warp_n*1152;
    const bf16* sKd = sm + KV_KD + warp_n*1152;
    const bf16* sVa = sm + KV_VA + warp_n*1536;
    const bf16* sVd = sm + KV_VD + warp_n*1536;

    // ---- per 16-row slab: repack acc -> Q frags, dual attention, write z ----
    #pragma unroll
    for (int mt = 0; mt < 4; mt++) {
        uint32_t qf[4][4];
        #pragma unroll
        for (int ks = 0; ks < 4; ks++) {
            qf[ks][0] = pack_bf2(acc[mt][2*ks][0],   acc[mt][2*ks][1]);
            qf[ks][1] = pack_bf2(acc[mt][2*ks][2],   acc[mt][2*ks][3]);
            qf[ks][2] = pack_bf2(acc[mt][2*ks+1][0], acc[mt][2*ks+1][1]);
            qf[ks][3] = pack_bf2(acc[mt][2*ks+1][2], acc[mt][2*ks+1][3]);
        }
        float out[8][4];
        #pragma unroll
        for (int n8 = 0; n8 < 8; n8++)
            #pragma unroll
            for (int r = 0; r < 4; r++) out[n8][r] = 0.f;

        attend_one(sKa, sVa, ga, lane, qf, out);
        attend_one(sKd, sVd, gd, lane, qf, out);

        long zb = ((long)(bm + warp_m*64 + mt*16 + (lane >> 2)))*Dsz
                + bn + warp_n*64 + 2*(lane & 3);
        #pragma unroll
        for (int n8 = 0; n8 < 8; n8++) {
            *(uint32_t*)(g_z + zb + n8*8)          = pack_bf2(out[n8][0], out[n8][1]);
            *(uint32_t*)(g_z + zb + 8*Dsz + n8*8)  = pack_bf2(out[n8][2], out[n8][3]);
        }
    }
}

// ---------------- fused prep: conversions + gather + gate -------------------
#define HID_BLK  10240
#define WQ_BLK   1600
#define WK_BLK   960
#define W_BLK    (2*WQ_BLK + 4*WK_BLK)   // 7040
#define GATH_BLK 1536
#define PREP_BLKS (HID_BLK + W_BLK + GATH_BLK + 32)

struct PrepArgs {
    const float* hidden;
    const float* enc;
    const float* src[6];
    bf16*        dst[6];
    const float* w_gate;
    const float* b_gate;
    const float* a_logit;
    const float* d_logit;
};

__global__ __launch_bounds__(256)
void prep_all(PrepArgs pa) {
    int bid = blockIdx.x;
    int tid = threadIdx.x;

    if (bid < HID_BLK) {
        int base = bid * 1024 + tid;
        float4 v0 = ((const float4*)pa.hidden)[base];
        float4 v1 = ((const float4*)pa.hidden)[base + 256];
        float4 v2 = ((const float4*)pa.hidden)[base + 512];
        float4 v3 = ((const float4*)pa.hidden)[base + 768];
        uint2 o0, o1, o2, o3;
        o0.x = pack_bf2(v0.x, v0.y); o0.y = pack_bf2(v0.z, v0.w);
        o1.x = pack_bf2(v1.x, v1.y); o1.y = pack_bf2(v1.z, v1.w);
        o2.x = pack_bf2(v2.x, v2.y); o2.y = pack_bf2(v2.z, v2.w);
        o3.x = pack_bf2(v3.x, v3.y); o3.y = pack_bf2(v3.z, v3.w);
        ((uint2*)g_hidb)[base]       = o0;
        ((uint2*)g_hidb)[base + 256] = o1;
        ((uint2*)g_hidb)[base + 512] = o2;
        ((uint2*)g_hidb)[base + 768] = o3;
        return;
    }
    bid -= HID_BLK;
    if (bid < W_BLK) {
        int seg, base;
        if (bid < WQ_BLK)               { seg = 0; base = bid; }
        else if (bid < 2*WQ_BLK)        { seg = 1; base = bid - WQ_BLK; }
        else { int y = bid - 2*WQ_BLK;    seg = 2 + y / WK_BLK; base = y % WK_BLK; }
        int i = base * 256 + tid;
        float4 v = ((const float4*)pa.src[seg])[i];
        uint2 o;
        o.x = pack_bf2(v.x, v.y);
        o.y = pack_bf2(v.z, v.w);
        ((uint2*)pa.dst[seg])[i] = o;
        return;
    }
    bid -= W_BLK;
    if (bid < GATH_BLK) {
        int i = bid * 256 + tid;
        int c = i % CRS;
        int tt = (i / CRS) % NTOK;
        int b = i / (CRS*NTOK);
        g_dis [i] = __float2bfloat16_rn(pa.enc[((long)b*ETOK + tt)        * CRS + c]);
        g_anat[i] = __float2bfloat16_rn(pa.enc[((long)b*ETOK + NTOK + tt) * CRS + c]);
        return;
    }
    bid -= GATH_BLK;
    {
        int b = bid;
        __shared__ float red[256];
        float partial = 0.f;
        for (int c = tid; c < CRS; c += 256) {
            float s = 0.f;
            #pragma unroll
            for (int t2 = 0; t2 < NTOK; t2++)
                s += pa.enc[((long)b*ETOK + t2) * CRS + c];
            partial += (s * (1.0f/NTOK)) * pa.w_gate[c];
        }
        red[tid] = partial;
        __syncthreads();
        for (int off = 128; off > 0; off >>= 1) {
            if (tid < off) red[tid] += red[tid + off];
            __syncthreads();
        }
        if (tid == 0) {
            float shift = red[0] + pa.b_gate[0];
            g_gate[b*2+0] = 1.0f / (1.0f + expf(-(pa.a_logit[0] - shift)));
            g_gate[b*2+1] = 1.0f / (1.0f + expf(-(pa.d_logit[0] + shift)));
        }
    }
}

// ---------------- launch ----------------------------------------------------
extern "C" void kernel_launch(void* const* d_in, const int* in_sizes, int n_in,
                              void* d_out, int out_size) {
    const float* hidden  = (const float*)d_in[0];
    const float* enc     = (const float*)d_in[1];
    const float* w_q     = (const float*)d_in[2];
    const float* w_k     = (const float*)d_in[3];
    const float* w_v     = (const float*)d_in[4];
    const float* w_k_dis = (const float*)d_in[5];
    const float* w_v_dis = (const float*)d_in[6];
    const float* w_gate  = (const float*)d_in[7];
    const float* b_gate  = (const float*)d_in[8];
    const float* a_logit = (const float*)d_in[9];
    const float* d_logit = (const float*)d_in[10];
    const float* w_out   = (const float*)d_in[11];
    const float* b_out   = (const float*)d_in[12];
    float* out = (float*)d_out;

    bf16 *anat_p, *dis_p, *z_p, *hidb_p, *wq_p, *wout_p, *wka_p, *wva_p, *wkd_p, *wvd_p;
    float *ka_p, *va_p, *kd_p, *vd_p;
    cudaGetSymbolAddress((void**)&anat_p, g_anat);
    cudaGetSymbolAddress((void**)&dis_p,  g_dis);
    cudaGetSymbolAddress((void**)&ka_p,   g_ka);
    cudaGetSymbolAddress((void**)&va_p,   g_va);
    cudaGetSymbolAddress((void**)&kd_p,   g_kd);
    cudaGetSymbolAddress((void**)&vd_p,   g_vd);
    cudaGetSymbolAddress((void**)&z_p,    g_z);
    cudaGetSymbolAddress((void**)&hidb_p, g_hidb);
    cudaGetSymbolAddress((void**)&wq_p,   g_wq);
    cudaGetSymbolAddress((void**)&wout_p, g_wout);
    cudaGetSymbolAddress((void**)&wka_p,  g_wka);
    cudaGetSymbolAddress((void**)&wva_p,  g_wva);
    cudaGetSymbolAddress((void**)&wkd_p,  g_wkd);
    cudaGetSymbolAddress((void**)&wvd_p,  g_wvd);

    cudaFuncSetAttribute(kv_proj,    cudaFuncAttributeMaxDynamicSharedMemorySize, GEMM_SMEM);
    cudaFuncSetAttribute(qproj_attn, cudaFuncAttributeMaxDynamicSharedMemorySize, GEMM_SMEM);
    cudaFuncSetAttribute(gemm_out,   cudaFuncAttributeMaxDynamicSharedMemorySize, GEMM_SMEM);

    // fused prep
    {
        PrepArgs pa;
        pa.hidden = hidden;  pa.enc = enc;
        pa.src[0] = w_q;     pa.dst[0] = wq_p;
        pa.src[1] = w_out;   pa.dst[1] = wout_p;
        pa.src[2] = w_k;     pa.dst[2] = wka_p;
        pa.src[3] = w_v;     pa.dst[3] = wva_p;
        pa.src[4] = w_k_dis; pa.dst[4] = wkd_p;
        pa.src[5] = w_v_dis; pa.dst[5] = wvd_p;
        pa.w_gate = w_gate;  pa.b_gate = b_gate;
        pa.a_logit = a_logit; pa.d_logit = d_logit;
        prep_all<<<PREP_BLKS, 256>>>(pa);
    }
    // KV projections (single wave, 160 CTAs)
    {
        KvBatch kb;
        kb.A[0] = anat_p; kb.W[0] = wka_p; kb.C[0] = ka_p;
        kb.A[1] = anat_p; kb.W[1] = wva_p; kb.C[1] = va_p;
        kb.A[2] = dis_p;  kb.W[2] = wkd_p; kb.C[2] = kd_p;
        kb.A[3] = dis_p;  kb.W[3] = wvd_p; kb.C[3] = vd_p;
        dim3 grid(Dsz/128, 16);
        kv_proj<<<grid, 256, GEMM_SMEM>>>(kb);
    }
    // fused Q projection + attention -> z
    {
        dim3 grid(Dsz/128, MS/128);
        qproj_attn<<<grid, 128, GEMM_SMEM>>>(hidb_p, wq_p);
    }
    // out projection + bias + residual
    {
        dim3 grid(Dsz/128, MS/128);
        gemm_out<<<grid, 256, GEMM_SMEM>>>(z_p, wout_p, out, b_out, hidden);
    }
}